// round 12
// baseline (speedup 1.0000x reference)
#include <cuda_runtime.h>
#include <math.h>

#define FIN 512
#define HD  16
#define CD  7
#define NMAX 100000
#define EMAX 3200000
#define TPB  256
#define CAP  96     // ELL width; max degree ~60 for Binomial(3.2M, 1e-5)

// ---------------- scratch (static device globals) ----------------
__device__ int   g_cnt [NMAX];        // degree histogram; zeroed by k_dinv
__device__ int   g_cur [NMAX];        // ELL fill cursor; zeroed by k_dinv
__device__ int   g_deg [NMAX];        // saved degree for agg loop bounds
__device__ float g_dinv[NMAX];
__device__ int2  g_ell [NMAX * CAP];  // ELL: {src, bitcast(dinv[src])}
__device__ float g_h1  [NMAX * HD];
__device__ float g_h2  [NMAX * 8];    // 7 classes padded to 8 (col7 == 0)

// ---------------- side stream / events (created before harness checkpoints) --
static cudaStream_t g_sideStream = 0;
static cudaEvent_t  g_evFork = 0, g_evJoin = 0;
namespace {
struct StreamInit {
    StreamInit() {
        cudaStreamCreateWithFlags(&g_sideStream, cudaStreamNonBlocking);
        cudaEventCreateWithFlags(&g_evFork, cudaEventDisableTiming);
        cudaEventCreateWithFlags(&g_evJoin, cudaEventDisableTiming);
    }
};
StreamInit g_streamInit;
}

// ---------------- GEMM1: h1 = x @ W1 (exact round-1 kernel, 69us measured) ----

__global__ __launch_bounds__(256) void k_gemm1(const float* __restrict__ x,
                                               const float* __restrict__ W1, int n) {
    __shared__ float4 sW[32 * 4];        // 32 k x 16 j
    __shared__ float  sX[256 * 33];      // 256 nodes x 32 k (+1 pad)

    const int t  = threadIdx.x;
    const int n0 = blockIdx.x * 256;
    const int ng = t >> 2;               // 0..63
    const int jg = t & 3;                // 0..3

    float acc[4][4];
#pragma unroll
    for (int a = 0; a < 4; a++)
#pragma unroll
        for (int b = 0; b < 4; b++) acc[a][b] = 0.0f;

    for (int k0 = 0; k0 < FIN; k0 += 32) {
        __syncthreads();
        if (t < 128) {
            sW[t] = *(const float4*)(W1 + (size_t)(k0 + (t >> 2)) * HD + (t & 3) * 4);
        }
#pragma unroll
        for (int i = 0; i < 8; i++) {
            int f    = t + 256 * i;
            int nl   = f >> 3;
            int kq   = f & 7;
            int node = n0 + nl;
            float4 v = make_float4(0.f, 0.f, 0.f, 0.f);
            if (node < n) v = *(const float4*)(x + (size_t)node * FIN + k0 + kq * 4);
            float* sp = &sX[nl * 33 + kq * 4];
            sp[0] = v.x; sp[1] = v.y; sp[2] = v.z; sp[3] = v.w;
        }
        __syncthreads();
#pragma unroll
        for (int k = 0; k < 32; k++) {
            float4 wv = sW[k * 4 + jg];
            float x0 = sX[(ng * 4 + 0) * 33 + k];
            float x1 = sX[(ng * 4 + 1) * 33 + k];
            float x2 = sX[(ng * 4 + 2) * 33 + k];
            float x3 = sX[(ng * 4 + 3) * 33 + k];
            acc[0][0] += x0 * wv.x; acc[0][1] += x0 * wv.y; acc[0][2] += x0 * wv.z; acc[0][3] += x0 * wv.w;
            acc[1][0] += x1 * wv.x; acc[1][1] += x1 * wv.y; acc[1][2] += x1 * wv.z; acc[1][3] += x1 * wv.w;
            acc[2][0] += x2 * wv.x; acc[2][1] += x2 * wv.y; acc[2][2] += x2 * wv.z; acc[2][3] += x2 * wv.w;
            acc[3][0] += x3 * wv.x; acc[3][1] += x3 * wv.y; acc[3][2] += x3 * wv.z; acc[3][3] += x3 * wv.w;
        }
    }
#pragma unroll
    for (int ni = 0; ni < 4; ni++) {
        int node = n0 + ng * 4 + ni;
        if (node < n)
            *(float4*)&g_h1[(size_t)node * HD + jg * 4] =
                make_float4(acc[ni][0], acc[ni][1], acc[ni][2], acc[ni][3]);
    }
}

// ---------------- degree count: 4 edges/thread for MLP ----------------

__global__ void k_cnt(const int* __restrict__ dst, int e) {
    int i = (blockIdx.x * blockDim.x + threadIdx.x) * 4;
    if (i + 3 < e) {
        int d0 = dst[i], d1 = dst[i + 1], d2 = dst[i + 2], d3 = dst[i + 3];
        atomicAdd(&g_cnt[d0], 1);
        atomicAdd(&g_cnt[d1], 1);
        atomicAdd(&g_cnt[d2], 1);
        atomicAdd(&g_cnt[d3], 1);
    } else {
        for (; i < e; i++) atomicAdd(&g_cnt[dst[i]], 1);
    }
}

// ---------------- dinv + state reset (replay-deterministic) ----------------
// Reads the degree histogram, emits dinv + deg, and zeroes both counters so
// every graph replay starts from the same state.

__global__ void k_dinv(int n) {
    int i = blockIdx.x * blockDim.x + threadIdx.x;
    if (i < n) {
        int c = g_cnt[i];
        g_deg[i]  = c;
        g_dinv[i] = rsqrtf((float)(c + 1));   // +1 self-loop
        g_cnt[i]  = 0;
        g_cur[i]  = 0;
    }
}

// ---------------- ELL fill: writes {src, dinv[src]} (no scan needed) --------
// Runs after k_dinv on the side stream, so g_dinv is ready and g_cur is zeroed.

__global__ void k_fill(const int* __restrict__ src, const int* __restrict__ dst, int e) {
    int i = (blockIdx.x * blockDim.x + threadIdx.x) * 4;
    if (i + 3 < e) {
        int s0 = src[i], s1 = src[i + 1], s2 = src[i + 2], s3 = src[i + 3];
        int d0 = dst[i], d1 = dst[i + 1], d2 = dst[i + 2], d3 = dst[i + 3];
        float m0 = g_dinv[s0], m1 = g_dinv[s1], m2 = g_dinv[s2], m3 = g_dinv[s3];
        int p0 = atomicAdd(&g_cur[d0], 1);
        int p1 = atomicAdd(&g_cur[d1], 1);
        int p2 = atomicAdd(&g_cur[d2], 1);
        int p3 = atomicAdd(&g_cur[d3], 1);
        if (p0 < CAP) g_ell[(size_t)d0 * CAP + p0] = make_int2(s0, __float_as_int(m0));
        if (p1 < CAP) g_ell[(size_t)d1 * CAP + p1] = make_int2(s1, __float_as_int(m1));
        if (p2 < CAP) g_ell[(size_t)d2 * CAP + p2] = make_int2(s2, __float_as_int(m2));
        if (p3 < CAP) g_ell[(size_t)d3 * CAP + p3] = make_int2(s3, __float_as_int(m3));
    } else {
        for (; i < e; i++) {
            int s = src[i];
            int pos = atomicAdd(&g_cur[dst[i]], 1);
            if (pos < CAP)
                g_ell[(size_t)dst[i] * CAP + pos] = make_int2(s, __float_as_int(g_dinv[s]));
        }
    }
}

// ---------------- agg layer 1 + fused layer-2 transform ----------------
// 4 lanes per node; lane c owns feats [4c,4c+4). 2-level load chain: ell -> h1.

__global__ __launch_bounds__(TPB) void k_agg1(const float* __restrict__ b1,
                                              const float* __restrict__ W2, int n) {
    __shared__ float sW2[HD * 8];
    __shared__ float sb1[HD];
    int t = threadIdx.x;
    if (t < HD * 8) {
        int j = t >> 3, cc = t & 7;
        sW2[t] = (cc < CD) ? W2[j * CD + cc] : 0.f;
    } else if (t < HD * 8 + HD) {
        sb1[t - HD * 8] = b1[t - HD * 8];
    }
    __syncthreads();

    int node = blockIdx.x * 64 + (t >> 2);
    int c = t & 3;
    bool valid = node < n;
    if (!valid) node = n - 1;

    float dv = g_dinv[node];
    float4 h = *(const float4*)(g_h1 + (size_t)node * HD + c * 4);
    float4 acc = make_float4(h.x * dv, h.y * dv, h.z * dv, h.w * dv);

    const int2* ep = g_ell + (size_t)node * CAP;
    int cnt = g_deg[node];
    if (cnt > CAP) cnt = CAP;
    int j = 0;
    for (; j + 1 < cnt; j += 2) {
        int2 e0 = ep[j], e1 = ep[j + 1];
        float m0 = __int_as_float(e0.y), m1 = __int_as_float(e1.y);
        float4 w0 = *(const float4*)(g_h1 + (size_t)e0.x * HD + c * 4);
        float4 w1 = *(const float4*)(g_h1 + (size_t)e1.x * HD + c * 4);
        acc.x += w0.x * m0 + w1.x * m1;
        acc.y += w0.y * m0 + w1.y * m1;
        acc.z += w0.z * m0 + w1.z * m1;
        acc.w += w0.w * m0 + w1.w * m1;
    }
    if (j < cnt) {
        int2 e0 = ep[j];
        float m0 = __int_as_float(e0.y);
        float4 w0 = *(const float4*)(g_h1 + (size_t)e0.x * HD + c * 4);
        acc.x += w0.x * m0; acc.y += w0.y * m0;
        acc.z += w0.z * m0; acc.w += w0.w * m0;
    }

    float q0 = fmaxf(acc.x * dv + sb1[c * 4 + 0], 0.f);
    float q1 = fmaxf(acc.y * dv + sb1[c * 4 + 1], 0.f);
    float q2 = fmaxf(acc.z * dv + sb1[c * 4 + 2], 0.f);
    float q3 = fmaxf(acc.w * dv + sb1[c * 4 + 3], 0.f);

    float p[8];
#pragma unroll
    for (int cc = 0; cc < 8; cc++) {
        p[cc] = q0 * sW2[(c * 4 + 0) * 8 + cc]
              + q1 * sW2[(c * 4 + 1) * 8 + cc]
              + q2 * sW2[(c * 4 + 2) * 8 + cc]
              + q3 * sW2[(c * 4 + 3) * 8 + cc];
    }
#pragma unroll
    for (int cc = 0; cc < 8; cc++) {
        p[cc] += __shfl_xor_sync(0xFFFFFFFFu, p[cc], 1);
        p[cc] += __shfl_xor_sync(0xFFFFFFFFu, p[cc], 2);
    }
    if (valid) {
        if (c == 0)
            *(float4*)(g_h2 + (size_t)node * 8)     = make_float4(p[0], p[1], p[2], p[3]);
        else if (c == 1)
            *(float4*)(g_h2 + (size_t)node * 8 + 4) = make_float4(p[4], p[5], p[6], 0.f);
    }
}

// ---------------- agg layer 2 + fused bias + log_softmax ----------------

__global__ __launch_bounds__(TPB) void k_agg2(const float* __restrict__ b2,
                                              float* __restrict__ out, int n) {
    __shared__ float sb2[8];
    int t = threadIdx.x;
    if (t < 8) sb2[t] = (t < CD) ? b2[t] : -1e30f;   // pad lane -> exp()==0
    __syncthreads();

    int node = blockIdx.x * 128 + (t >> 1);
    int c = t & 1;
    bool valid = node < n;
    if (!valid) node = n - 1;

    float dv = g_dinv[node];
    float4 h = *(const float4*)(g_h2 + (size_t)node * 8 + c * 4);
    float4 acc = make_float4(h.x * dv, h.y * dv, h.z * dv, h.w * dv);

    const int2* ep = g_ell + (size_t)node * CAP;
    int cnt = g_deg[node];
    if (cnt > CAP) cnt = CAP;
    int j = 0;
    for (; j + 1 < cnt; j += 2) {
        int2 e0 = ep[j], e1 = ep[j + 1];
        float m0 = __int_as_float(e0.y), m1 = __int_as_float(e1.y);
        float4 w0 = *(const float4*)(g_h2 + (size_t)e0.x * 8 + c * 4);
        float4 w1 = *(const float4*)(g_h2 + (size_t)e1.x * 8 + c * 4);
        acc.x += w0.x * m0 + w1.x * m1;
        acc.y += w0.y * m0 + w1.y * m1;
        acc.z += w0.z * m0 + w1.z * m1;
        acc.w += w0.w * m0 + w1.w * m1;
    }
    if (j < cnt) {
        int2 e0 = ep[j];
        float m0 = __int_as_float(e0.y);
        float4 w0 = *(const float4*)(g_h2 + (size_t)e0.x * 8 + c * 4);
        acc.x += w0.x * m0; acc.y += w0.y * m0;
        acc.z += w0.z * m0; acc.w += w0.w * m0;
    }

    float o0 = acc.x * dv + sb2[c * 4 + 0];
    float o1 = acc.y * dv + sb2[c * 4 + 1];
    float o2 = acc.z * dv + sb2[c * 4 + 2];
    float o3 = acc.w * dv + sb2[c * 4 + 3];

    float m = fmaxf(fmaxf(o0, o1), fmaxf(o2, o3));
    m = fmaxf(m, __shfl_xor_sync(0xFFFFFFFFu, m, 1));
    float s = expf(o0 - m) + expf(o1 - m) + expf(o2 - m) + expf(o3 - m);
    s += __shfl_xor_sync(0xFFFFFFFFu, s, 1);
    float l = m + logf(s);

    if (valid) {
        float* op = out + (size_t)node * CD + c * 4;
        op[0] = o0 - l; op[1] = o1 - l; op[2] = o2 - l;
        if (c == 0) op[3] = o3 - l;
    }
}

// ---------------- launch: GEMM on main stream || ELL build on side stream ----

extern "C" void kernel_launch(void* const* d_in, const int* in_sizes, int n_in,
                              void* d_out, int out_size) {
    const float* x  = (const float*)d_in[0];
    const int*   ei = (const int*)  d_in[1];
    const float* W1 = (const float*)d_in[2];
    const float* b1 = (const float*)d_in[3];
    const float* W2 = (const float*)d_in[4];
    const float* b2 = (const float*)d_in[5];

    const int n = in_sizes[0] / FIN;
    const int e = in_sizes[1] / 2;
    const int* src = ei;
    const int* dst = ei + e;

    const int nbE4 = (e / 4 + TPB - 1) / TPB + 1;

    // fork: side stream builds the ELL adjacency while main stream runs the GEMM
    cudaEventRecord(g_evFork, 0);
    cudaStreamWaitEvent(g_sideStream, g_evFork, 0);

    k_cnt  <<<nbE4, TPB, 0, g_sideStream>>>(dst, e);
    k_dinv <<<(n + TPB - 1) / TPB, TPB, 0, g_sideStream>>>(n);
    k_fill <<<nbE4, TPB, 0, g_sideStream>>>(src, dst, e);
    cudaEventRecord(g_evJoin, g_sideStream);

    k_gemm1<<<(n + 255) / 256, TPB>>>(x, W1, n);

    // join: aggregation needs both h1 (main) and the ELL adjacency (side)
    cudaStreamWaitEvent(0, g_evJoin, 0);
    k_agg1 <<<(n + 63) / 64, TPB>>>(b1, W2, n);
    k_agg2 <<<(n + 127) / 128, TPB>>>(b2, (float*)d_out, n);
}

// round 13
// speedup vs baseline: 1.0626x; 1.0626x over previous
#include <cuda_runtime.h>
#include <math.h>

#define FIN 512
#define HD  16
#define CD  7
#define NMAX 100000
#define EMAX 3200000
#define TPB  256

// ---------------- scratch (static device globals) ----------------
__device__ int   g_cnt [NMAX];        // in-degree (w/o self-loop); re-zeroed by scan3
__device__ int   g_rows[NMAX + 1];    // CSR row starts (+ total at [n])
__device__ int   g_cur [NMAX];        // fill cursor
__device__ int   g_bsum[128];         // scan block sums
__device__ float g_dinv[NMAX];
__device__ int2  g_edge[EMAX];        // CSR: {src, bitcast(dinv[src])}
__device__ float g_h1  [NMAX * HD];
__device__ float g_h2  [NMAX * 8];    // 7 classes padded to 8 (col7 == 0)

// ---------------- side stream / events (created before harness checkpoints) --
static cudaStream_t g_sideStream = 0;
static cudaEvent_t  g_evFork = 0, g_evJoin = 0;
namespace {
struct StreamInit {
    StreamInit() {
        int lo, hi;
        cudaDeviceGetStreamPriorityRange(&lo, &hi);   // hi = highest priority
        cudaStreamCreateWithPriority(&g_sideStream, cudaStreamNonBlocking, hi);
        cudaEventCreateWithFlags(&g_evFork, cudaEventDisableTiming);
        cudaEventCreateWithFlags(&g_evJoin, cudaEventDisableTiming);
    }
};
StreamInit g_streamInit;
}

// ---------------- GEMM1: h1 = x @ W1 (exact round-1 kernel, 69us measured) ----

__global__ __launch_bounds__(256) void k_gemm1(const float* __restrict__ x,
                                               const float* __restrict__ W1, int n) {
    __shared__ float4 sW[32 * 4];        // 32 k x 16 j
    __shared__ float  sX[256 * 33];      // 256 nodes x 32 k (+1 pad)

    const int t  = threadIdx.x;
    const int n0 = blockIdx.x * 256;
    const int ng = t >> 2;               // 0..63
    const int jg = t & 3;                // 0..3

    float acc[4][4];
#pragma unroll
    for (int a = 0; a < 4; a++)
#pragma unroll
        for (int b = 0; b < 4; b++) acc[a][b] = 0.0f;

    for (int k0 = 0; k0 < FIN; k0 += 32) {
        __syncthreads();
        if (t < 128) {
            sW[t] = *(const float4*)(W1 + (size_t)(k0 + (t >> 2)) * HD + (t & 3) * 4);
        }
#pragma unroll
        for (int i = 0; i < 8; i++) {
            int f    = t + 256 * i;
            int nl   = f >> 3;
            int kq   = f & 7;
            int node = n0 + nl;
            float4 v = make_float4(0.f, 0.f, 0.f, 0.f);
            if (node < n) v = *(const float4*)(x + (size_t)node * FIN + k0 + kq * 4);
            float* sp = &sX[nl * 33 + kq * 4];
            sp[0] = v.x; sp[1] = v.y; sp[2] = v.z; sp[3] = v.w;
        }
        __syncthreads();
#pragma unroll
        for (int k = 0; k < 32; k++) {
            float4 wv = sW[k * 4 + jg];
            float x0 = sX[(ng * 4 + 0) * 33 + k];
            float x1 = sX[(ng * 4 + 1) * 33 + k];
            float x2 = sX[(ng * 4 + 2) * 33 + k];
            float x3 = sX[(ng * 4 + 3) * 33 + k];
            acc[0][0] += x0 * wv.x; acc[0][1] += x0 * wv.y; acc[0][2] += x0 * wv.z; acc[0][3] += x0 * wv.w;
            acc[1][0] += x1 * wv.x; acc[1][1] += x1 * wv.y; acc[1][2] += x1 * wv.z; acc[1][3] += x1 * wv.w;
            acc[2][0] += x2 * wv.x; acc[2][1] += x2 * wv.y; acc[2][2] += x2 * wv.z; acc[2][3] += x2 * wv.w;
            acc[3][0] += x3 * wv.x; acc[3][1] += x3 * wv.y; acc[3][2] += x3 * wv.z; acc[3][3] += x3 * wv.w;
        }
    }
#pragma unroll
    for (int ni = 0; ni < 4; ni++) {
        int node = n0 + ng * 4 + ni;
        if (node < n)
            *(float4*)&g_h1[(size_t)node * HD + jg * 4] =
                make_float4(acc[ni][0], acc[ni][1], acc[ni][2], acc[ni][3]);
    }
}

// ---------------- degree count: 4 edges/thread for MLP ----------------

__global__ void k_cnt(const int* __restrict__ dst, int e) {
    int i = (blockIdx.x * blockDim.x + threadIdx.x) * 4;
    if (i + 3 < e) {
        int d0 = dst[i], d1 = dst[i + 1], d2 = dst[i + 2], d3 = dst[i + 3];
        atomicAdd(&g_cnt[d0], 1);
        atomicAdd(&g_cnt[d1], 1);
        atomicAdd(&g_cnt[d2], 1);
        atomicAdd(&g_cnt[d3], 1);
    } else {
        for (; i < e; i++) atomicAdd(&g_cnt[dst[i]], 1);
    }
}

// ---------------- 3-kernel scan (no co-residency requirement) ----------------
// scan1: per-block scan of 1024 counts + dinv. scan2: scan of block sums.
// scan3: add offsets, init cursors, re-zero counts (replay-deterministic).

__global__ __launch_bounds__(TPB) void k_scan1(int n) {
    __shared__ int s[256];
    const int t = threadIdx.x;
    const int b = blockIdx.x;
    int base = b * 1024 + t * 4;
    int v0 = (base + 0 < n) ? g_cnt[base + 0] : 0;
    int v1 = (base + 1 < n) ? g_cnt[base + 1] : 0;
    int v2 = (base + 2 < n) ? g_cnt[base + 2] : 0;
    int v3 = (base + 3 < n) ? g_cnt[base + 3] : 0;
    if (base + 0 < n) g_dinv[base + 0] = rsqrtf((float)(v0 + 1));
    if (base + 1 < n) g_dinv[base + 1] = rsqrtf((float)(v1 + 1));
    if (base + 2 < n) g_dinv[base + 2] = rsqrtf((float)(v2 + 1));
    if (base + 3 < n) g_dinv[base + 3] = rsqrtf((float)(v3 + 1));
    int ts = v0 + v1 + v2 + v3;
    s[t] = ts;
    __syncthreads();
#pragma unroll
    for (int off = 1; off < 256; off <<= 1) {
        int xv = (t >= off) ? s[t - off] : 0;
        __syncthreads();
        s[t] += xv;
        __syncthreads();
    }
    int r = s[t] - ts;
    if (t == 255) g_bsum[b] = s[255];
    if (base + 0 < n) { g_rows[base + 0] = r; r += v0; }
    if (base + 1 < n) { g_rows[base + 1] = r; r += v1; }
    if (base + 2 < n) { g_rows[base + 2] = r; r += v2; }
    if (base + 3 < n) { g_rows[base + 3] = r; }
}

__global__ void k_scan2(int nb) {   // one block; nb <= 128
    __shared__ int s[128];
    int t = threadIdx.x;
    int v = (t < nb) ? g_bsum[t] : 0;
    s[t] = v;
    __syncthreads();
#pragma unroll
    for (int off = 1; off < 128; off <<= 1) {
        int xv = (t >= off) ? s[t - off] : 0;
        __syncthreads();
        s[t] += xv;
        __syncthreads();
    }
    if (t < nb) g_bsum[t] = s[t] - v;   // exclusive
}

__global__ void k_scan3(int n, int e) {
    int i = blockIdx.x * blockDim.x + threadIdx.x;
    if (i < n) {
        int r = g_rows[i] + g_bsum[i >> 10];
        g_rows[i] = r;
        g_cur[i]  = r;
        g_cnt[i]  = 0;          // replay-deterministic reset
    }
    if (i == 0) g_rows[n] = e;  // total edge count
}

// ---------------- CSR fill: writes {src, dinv[src]} ----------------

__global__ void k_fill(const int* __restrict__ src, const int* __restrict__ dst, int e) {
    int i = (blockIdx.x * blockDim.x + threadIdx.x) * 4;
    if (i + 3 < e) {
        int s0 = src[i], s1 = src[i + 1], s2 = src[i + 2], s3 = src[i + 3];
        int d0 = dst[i], d1 = dst[i + 1], d2 = dst[i + 2], d3 = dst[i + 3];
        float m0 = g_dinv[s0], m1 = g_dinv[s1], m2 = g_dinv[s2], m3 = g_dinv[s3];
        int p0 = atomicAdd(&g_cur[d0], 1);
        int p1 = atomicAdd(&g_cur[d1], 1);
        int p2 = atomicAdd(&g_cur[d2], 1);
        int p3 = atomicAdd(&g_cur[d3], 1);
        g_edge[p0] = make_int2(s0, __float_as_int(m0));
        g_edge[p1] = make_int2(s1, __float_as_int(m1));
        g_edge[p2] = make_int2(s2, __float_as_int(m2));
        g_edge[p3] = make_int2(s3, __float_as_int(m3));
    } else {
        for (; i < e; i++) {
            int s = src[i];
            int pos = atomicAdd(&g_cur[dst[i]], 1);
            g_edge[pos] = make_int2(s, __float_as_int(g_dinv[s]));
        }
    }
}

// ---------------- agg layer 1 + fused layer-2 transform ----------------
// 4 lanes per node; lane c owns feats [4c,4c+4). 2-level load chain: edge -> h1.

__global__ __launch_bounds__(TPB) void k_agg1(const float* __restrict__ b1,
                                              const float* __restrict__ W2, int n) {
    __shared__ float sW2[HD * 8];
    __shared__ float sb1[HD];
    int t = threadIdx.x;
    if (t < HD * 8) {
        int j = t >> 3, cc = t & 7;
        sW2[t] = (cc < CD) ? W2[j * CD + cc] : 0.f;
    } else if (t < HD * 8 + HD) {
        sb1[t - HD * 8] = b1[t - HD * 8];
    }
    __syncthreads();

    int node = blockIdx.x * 64 + (t >> 2);
    int c = t & 3;
    bool valid = node < n;
    if (!valid) node = n - 1;

    float dv = g_dinv[node];
    float4 h = *(const float4*)(g_h1 + (size_t)node * HD + c * 4);
    float4 acc = make_float4(h.x * dv, h.y * dv, h.z * dv, h.w * dv);

    int st = g_rows[node];
    int cnt = g_rows[node + 1] - st;
    int j = 0;
    for (; j + 1 < cnt; j += 2) {
        int2 e0 = g_edge[st + j], e1 = g_edge[st + j + 1];
        float m0 = __int_as_float(e0.y), m1 = __int_as_float(e1.y);
        float4 w0 = *(const float4*)(g_h1 + (size_t)e0.x * HD + c * 4);
        float4 w1 = *(const float4*)(g_h1 + (size_t)e1.x * HD + c * 4);
        acc.x += w0.x * m0 + w1.x * m1;
        acc.y += w0.y * m0 + w1.y * m1;
        acc.z += w0.z * m0 + w1.z * m1;
        acc.w += w0.w * m0 + w1.w * m1;
    }
    if (j < cnt) {
        int2 e0 = g_edge[st + j];
        float m0 = __int_as_float(e0.y);
        float4 w0 = *(const float4*)(g_h1 + (size_t)e0.x * HD + c * 4);
        acc.x += w0.x * m0; acc.y += w0.y * m0;
        acc.z += w0.z * m0; acc.w += w0.w * m0;
    }

    float q0 = fmaxf(acc.x * dv + sb1[c * 4 + 0], 0.f);
    float q1 = fmaxf(acc.y * dv + sb1[c * 4 + 1], 0.f);
    float q2 = fmaxf(acc.z * dv + sb1[c * 4 + 2], 0.f);
    float q3 = fmaxf(acc.w * dv + sb1[c * 4 + 3], 0.f);

    float p[8];
#pragma unroll
    for (int cc = 0; cc < 8; cc++) {
        p[cc] = q0 * sW2[(c * 4 + 0) * 8 + cc]
              + q1 * sW2[(c * 4 + 1) * 8 + cc]
              + q2 * sW2[(c * 4 + 2) * 8 + cc]
              + q3 * sW2[(c * 4 + 3) * 8 + cc];
    }
#pragma unroll
    for (int cc = 0; cc < 8; cc++) {
        p[cc] += __shfl_xor_sync(0xFFFFFFFFu, p[cc], 1);
        p[cc] += __shfl_xor_sync(0xFFFFFFFFu, p[cc], 2);
    }
    if (valid) {
        if (c == 0)
            *(float4*)(g_h2 + (size_t)node * 8)     = make_float4(p[0], p[1], p[2], p[3]);
        else if (c == 1)
            *(float4*)(g_h2 + (size_t)node * 8 + 4) = make_float4(p[4], p[5], p[6], 0.f);
    }
}

// ---------------- agg layer 2 + fused bias + log_softmax ----------------

__global__ __launch_bounds__(TPB) void k_agg2(const float* __restrict__ b2,
                                              float* __restrict__ out, int n) {
    __shared__ float sb2[8];
    int t = threadIdx.x;
    if (t < 8) sb2[t] = (t < CD) ? b2[t] : -1e30f;   // pad lane -> exp()==0
    __syncthreads();

    int node = blockIdx.x * 128 + (t >> 1);
    int c = t & 1;
    bool valid = node < n;
    if (!valid) node = n - 1;

    float dv = g_dinv[node];
    float4 h = *(const float4*)(g_h2 + (size_t)node * 8 + c * 4);
    float4 acc = make_float4(h.x * dv, h.y * dv, h.z * dv, h.w * dv);

    int st = g_rows[node];
    int cnt = g_rows[node + 1] - st;
    int j = 0;
    for (; j + 1 < cnt; j += 2) {
        int2 e0 = g_edge[st + j], e1 = g_edge[st + j + 1];
        float m0 = __int_as_float(e0.y), m1 = __int_as_float(e1.y);
        float4 w0 = *(const float4*)(g_h2 + (size_t)e0.x * 8 + c * 4);
        float4 w1 = *(const float4*)(g_h2 + (size_t)e1.x * 8 + c * 4);
        acc.x += w0.x * m0 + w1.x * m1;
        acc.y += w0.y * m0 + w1.y * m1;
        acc.z += w0.z * m0 + w1.z * m1;
        acc.w += w0.w * m0 + w1.w * m1;
    }
    if (j < cnt) {
        int2 e0 = g_edge[st + j];
        float m0 = __int_as_float(e0.y);
        float4 w0 = *(const float4*)(g_h2 + (size_t)e0.x * 8 + c * 4);
        acc.x += w0.x * m0; acc.y += w0.y * m0;
        acc.z += w0.z * m0; acc.w += w0.w * m0;
    }

    float o0 = acc.x * dv + sb2[c * 4 + 0];
    float o1 = acc.y * dv + sb2[c * 4 + 1];
    float o2 = acc.z * dv + sb2[c * 4 + 2];
    float o3 = acc.w * dv + sb2[c * 4 + 3];

    float m = fmaxf(fmaxf(o0, o1), fmaxf(o2, o3));
    m = fmaxf(m, __shfl_xor_sync(0xFFFFFFFFu, m, 1));
    float s = expf(o0 - m) + expf(o1 - m) + expf(o2 - m) + expf(o3 - m);
    s += __shfl_xor_sync(0xFFFFFFFFu, s, 1);
    float l = m + logf(s);

    if (valid) {
        float* op = out + (size_t)node * CD + c * 4;
        op[0] = o0 - l; op[1] = o1 - l; op[2] = o2 - l;
        if (c == 0) op[3] = o3 - l;
    }
}

// ---------------- launch: GEMM on main stream || CSR chain on side stream ----

extern "C" void kernel_launch(void* const* d_in, const int* in_sizes, int n_in,
                              void* d_out, int out_size) {
    const float* x  = (const float*)d_in[0];
    const int*   ei = (const int*)  d_in[1];
    const float* W1 = (const float*)d_in[2];
    const float* b1 = (const float*)d_in[3];
    const float* W2 = (const float*)d_in[4];
    const float* b2 = (const float*)d_in[5];

    const int n = in_sizes[0] / FIN;
    const int e = in_sizes[1] / 2;
    const int* src = ei;
    const int* dst = ei + e;

    const int nbScan = (n + 1023) / 1024;  // 98
    const int nbE4   = (e / 4 + TPB - 1) / TPB + 1;

    // fork: side stream builds the CSR while main stream runs the GEMM
    cudaEventRecord(g_evFork, 0);
    cudaStreamWaitEvent(g_sideStream, g_evFork, 0);

    k_cnt   <<<nbE4, TPB, 0, g_sideStream>>>(dst, e);
    k_scan1 <<<nbScan, TPB, 0, g_sideStream>>>(n);
    k_scan2 <<<1, 128, 0, g_sideStream>>>(nbScan);
    k_scan3 <<<(n + TPB - 1) / TPB, TPB, 0, g_sideStream>>>(n, e);
    k_fill  <<<nbE4, TPB, 0, g_sideStream>>>(src, dst, e);
    cudaEventRecord(g_evJoin, g_sideStream);

    k_gemm1 <<<(n + 255) / 256, TPB>>>(x, W1, n);

    // join: aggregation needs both h1 (main) and the CSR (side)
    cudaStreamWaitEvent(0, g_evJoin, 0);
    k_agg1  <<<(n + 63) / 64, TPB>>>(b1, W2, n);
    k_agg2  <<<(n + 127) / 128, TPB>>>(b2, (float*)d_out, n);
}